// round 1
// baseline (speedup 1.0000x reference)
#include <cuda_runtime.h>
#include <cstdint>

// Problem constants
#define BB 512
#define TT 1024
#define DD 64
#define HH 128
#define GG 384   // 3*H

// Scratch for precomputed input gates, layout [t][b][g] (coalesced per-step reads)
__device__ float g_xg[(size_t)TT * BB * GG];

// ---------- packed fp32x2 helpers (PTX-only; ptxas won't auto-fuse) ----------
__device__ __forceinline__ unsigned long long ffma2(unsigned long long a,
                                                    unsigned long long b,
                                                    unsigned long long c) {
    unsigned long long d;
    asm("fma.rn.f32x2 %0, %1, %2, %3;" : "=l"(d) : "l"(a), "l"(b), "l"(c));
    return d;
}
__device__ __forceinline__ float f2sum(unsigned long long v) {
    float lo, hi;
    asm("mov.b64 {%0, %1}, %2;" : "=f"(lo), "=f"(hi) : "l"(v));
    return lo + hi;
}
__device__ __forceinline__ float sigmoidf_(float x) {
    return __fdividef(1.0f, 1.0f + __expf(-x));
}

// ============================================================================
// Kernel 1: xg[t][b][g] = b_ih[g] + sum_d x[b][t][d] * w_ih[g][d]
// Grid: 4096 CTAs (t, 128-row batch chunk), 384 threads (one per gate row g).
// w_ih row held in registers (32 x f32x2); x rows staged in smem, broadcast.
// ============================================================================
__global__ void __launch_bounds__(GG) xg_kernel(const float* __restrict__ x,
                                                const float* __restrict__ w_ih,
                                                const float* __restrict__ b_ih) {
    __shared__ __align__(16) float xs[128 * DD];  // 32 KB

    const int t  = blockIdx.x >> 2;
    const int b0 = (blockIdx.x & 3) * 128;
    const int g  = threadIdx.x;

    // Stage 128 rows of x (64 contiguous floats each) into smem
    const float4* x4 = reinterpret_cast<const float4*>(x);
    float4* xs4 = reinterpret_cast<float4*>(xs);
    for (int i = threadIdx.x; i < 128 * 16; i += GG) {
        int row = i >> 4, c4 = i & 15;
        xs4[i] = x4[((size_t)(b0 + row) * TT + t) * 16 + c4];
    }

    // Load this thread's w_ih row into registers as packed pairs
    unsigned long long wq[32];
    const unsigned long long* wp =
        reinterpret_cast<const unsigned long long*>(w_ih + (size_t)g * DD);
#pragma unroll
    for (int i = 0; i < 32; i++) wq[i] = wp[i];
    const unsigned long long accInit =
        (unsigned long long)__float_as_uint(b_ih[g]);  // (bias, 0)

    __syncthreads();

    float* outp = g_xg + ((size_t)t * BB + b0) * GG + g;
    for (int row = 0; row < 128; row++) {
        const ulonglong2* hx =
            reinterpret_cast<const ulonglong2*>(xs + row * DD);
        unsigned long long acc = accInit;
#pragma unroll
        for (int i = 0; i < 16; i++) {
            ulonglong2 v = hx[i];  // broadcast LDS.128
            acc = ffma2(wq[2 * i], v.x, acc);
            acc = ffma2(wq[2 * i + 1], v.y, acc);
        }
        outp[(size_t)row * GG] = f2sum(acc);
    }
}

// ============================================================================
// Kernel 2: persistent GRU recurrence. 128 CTAs x 4 batch rows, 384 threads.
// Thread g owns gate row g: w_hh[g][0:128] in 64 f32x2 registers.
// h lives in smem; per step: 32 x (4 broadcast LDS.128 + 8 FFMA2) per thread.
// ============================================================================
__global__ void __launch_bounds__(GG) gru_kernel(const float* __restrict__ mask,
                                                 const float* __restrict__ w_hh,
                                                 const float* __restrict__ b_hh,
                                                 const float* __restrict__ Wo,
                                                 const float* __restrict__ bo,
                                                 float* __restrict__ out) {
    __shared__ __align__(16) float h_s[4][HH];
    __shared__ float gsum[4][GG];
    __shared__ float xn_s[4][HH];
    __shared__ float m_s[4];
    __shared__ float wo_s[2][HH];

    const int tid = threadIdx.x;
    const int g   = tid;
    const int b0  = blockIdx.x * 4;

    // init h = 0, stage Wo
    for (int i = tid; i < 4 * HH; i += GG) (&h_s[0][0])[i] = 0.0f;
    for (int i = tid; i < 2 * HH; i += GG) (&wo_s[0][0])[i] = Wo[i];

    // w_hh row g -> registers (64 packed pairs = 128 floats)
    unsigned long long wq[64];
    const unsigned long long* wp =
        reinterpret_cast<const unsigned long long*>(w_hh + (size_t)g * HH);
#pragma unroll
    for (int i = 0; i < 64; i++) wq[i] = wp[i];
    const unsigned long long accInit =
        (unsigned long long)__float_as_uint(b_hh[g]);  // (b_hh, 0)

    const float* xgp = g_xg + (size_t)b0 * GG + g;  // advance by B*G per step
    const float* mp  = (tid < 4) ? (mask + (size_t)(b0 + tid) * TT) : mask;
    const float bo0 = bo[0], bo1 = bo[1];

    __syncthreads();

    for (int t = 0; t < TT; t++) {
        // prefetch xg for this step (4 rows) and mask
        float xg0 = xgp[0];
        float xg1 = xgp[GG];
        float xg2 = xgp[2 * GG];
        float xg3 = xgp[3 * GG];
        if (tid < 4) m_s[tid] = mp[t];

        // hg[b] = b_hh[g] + dot(h[b], w_hh[g])
        unsigned long long a0 = accInit, a1 = accInit, a2 = accInit, a3 = accInit;
        const ulonglong2* h0p = reinterpret_cast<const ulonglong2*>(h_s[0]);
        const ulonglong2* h1p = reinterpret_cast<const ulonglong2*>(h_s[1]);
        const ulonglong2* h2p = reinterpret_cast<const ulonglong2*>(h_s[2]);
        const ulonglong2* h3p = reinterpret_cast<const ulonglong2*>(h_s[3]);
#pragma unroll
        for (int i = 0; i < 32; i++) {
            ulonglong2 v0 = h0p[i];
            a0 = ffma2(wq[2 * i], v0.x, a0);
            a0 = ffma2(wq[2 * i + 1], v0.y, a0);
            ulonglong2 v1 = h1p[i];
            a1 = ffma2(wq[2 * i], v1.x, a1);
            a1 = ffma2(wq[2 * i + 1], v1.y, a1);
            ulonglong2 v2 = h2p[i];
            a2 = ffma2(wq[2 * i], v2.x, a2);
            a2 = ffma2(wq[2 * i + 1], v2.y, a2);
            ulonglong2 v3 = h3p[i];
            a3 = ffma2(wq[2 * i], v3.x, a3);
            a3 = ffma2(wq[2 * i + 1], v3.y, a3);
        }
        float hg0 = f2sum(a0), hg1 = f2sum(a1), hg2 = f2sum(a2), hg3 = f2sum(a3);

        if (g < 2 * HH) {  // r,z gates: store xg+hg
            gsum[0][g] = xg0 + hg0;
            gsum[1][g] = xg1 + hg1;
            gsum[2][g] = xg2 + hg2;
            gsum[3][g] = xg3 + hg3;
        } else {           // n gate: keep hn and xn separate (n = tanh(xn + r*hn))
            gsum[0][g] = hg0;  xn_s[0][g - 2 * HH] = xg0;
            gsum[1][g] = hg1;  xn_s[1][g - 2 * HH] = xg1;
            gsum[2][g] = hg2;  xn_s[2][g - 2 * HH] = xg2;
            gsum[3][g] = hg3;  xn_s[3][g - 2 * HH] = xg3;
        }
        __syncthreads();

        // elementwise combine: 512 (b,j) cells over 384 threads
        {
            int idx = tid;
#pragma unroll
            for (int rep = 0; rep < 2; rep++) {
                if (idx < 512) {
                    int b = idx >> 7, j = idx & 127;
                    float r  = sigmoidf_(gsum[b][j]);
                    float z  = sigmoidf_(gsum[b][j + HH]);
                    float n  = tanhf(fmaf(r, gsum[b][j + 2 * HH], xn_s[b][j]));
                    float ho = h_s[b][j];
                    float hn = fmaf(z, ho - n, n);       // (1-z)*n + z*ho
                    float m  = m_s[b];
                    h_s[b][j] = fmaf(m, hn - ho, ho);    // m*hn + (1-m)*ho
                }
                idx += GG;
            }
        }
        __syncthreads();

        // logits: 8 warps, one per (b, o); warp-reduce 128-dot
        if (tid < 256) {
            int w = tid >> 5, lane = tid & 31;
            int b = w >> 1, o = w & 1;
            float p = 0.0f;
#pragma unroll
            for (int q = 0; q < 4; q++)
                p = fmaf(h_s[b][lane + 32 * q], wo_s[o][lane + 32 * q], p);
#pragma unroll
            for (int off = 16; off; off >>= 1)
                p += __shfl_down_sync(0xffffffffu, p, off);
            if (lane == 0)
                out[(((size_t)(b0 + b)) * TT + t) * 2 + o] = p + (o ? bo1 : bo0);
        }

        xgp += (size_t)BB * GG;
    }
}

// ============================================================================
extern "C" void kernel_launch(void* const* d_in, const int* in_sizes, int n_in,
                              void* d_out, int out_size) {
    const float* x    = (const float*)d_in[0];
    const float* mask = (const float*)d_in[1];
    const float* w_ih = (const float*)d_in[2];
    const float* w_hh = (const float*)d_in[3];
    const float* b_ih = (const float*)d_in[4];
    const float* b_hh = (const float*)d_in[5];
    const float* Wo   = (const float*)d_in[6];
    const float* bo   = (const float*)d_in[7];
    float* out = (float*)d_out;

    xg_kernel<<<TT * 4, GG>>>(x, w_ih, b_ih);
    gru_kernel<<<BB / 4, GG>>>(mask, w_hh, b_hh, Wo, bo, out);
}